// round 16
// baseline (speedup 1.0000x reference)
#include <cuda_runtime.h>
#include <cuda_bf16.h>

// Problem constants
#define NB    4
#define NC    2000      // curves per batch
#define NLS   2000      // line samples per batch
#define NS    4000      // surfaces per batch
#define NF    8000      // faces per batch
#define NTS   26000     // triangle samples per batch
#define NPT   (NC + NLS + NS + NTS)   // 34000 points per batch
#define NPTOT (NB * NPT)              // 136000 points total
#define OG    258       // occ grid edge (256 + 2*2 pad - 3 + 1)
#define OGSQ  (OG * OG)                        // 66564
#define X_ELEMS   (NB * NPT * 3)               // 408000
#define OCC_PER_B 17173512L                    // OG^3, divisible by 4
#define OCC_ELEMS (NB * OCC_PER_B)             // 68,669,448

#define N4_PER_B ((int)(OCC_PER_B / 4))        // 4,293,378 float4 per slab
#define ZGB      4144                          // zero blocks (28/SM), ~4 f4/thread
#define PTBLK    ((NPTOT + 255) / 256)         // 532 points blocks
#define NPT2     (NPT / 2)                     // 17000
#define SCTHREADS (9 * NPT2)                   // 153000 (2 points per thread)
#define SCB      ((SCTHREADS + 255) / 256)     // 598 scatter blocks

// Scratch: packed voxel coords per point (c0 | c1<<8 | c2<<16).
__device__ int g_coords[NPTOT];

__device__ __forceinline__ int cube_coord(float p) {
    float t = __fadd_rn(__fmul_rn(p, 256.0f), 128.5f);
    t = fminf(255.0f, fmaxf(0.0f, t));
    return (int)t;   // t >= 0 so truncation == floor
}

// ---------------------------------------------------------------------------
// points job: one thread per point. Exact f32 op order of the reference
// (no FMA contraction). Writes x and the packed voxel coord.
// ---------------------------------------------------------------------------
__device__ __forceinline__ void points_job(int idx,
                              const float* __restrict__ curves,
                              const float* __restrict__ surfaces,
                              const float* __restrict__ t_line,
                              const float* __restrict__ uv,
                              const int*   __restrict__ lines_array,
                              const int*   __restrict__ faces_array,
                              const int*   __restrict__ line_choice,
                              const int*   __restrict__ tri_choice,
                              float* __restrict__ out) {
    int b = idx / NPT;
    int j = idx - b * NPT;

    float p0, p1, p2;

    if (j < NC) {
        // segment 0: curves passthrough
        const float* c = curves + ((long)(b * NC + j)) * 3;
        p0 = c[0]; p1 = c[1]; p2 = c[2];
    } else if (j < NC + NLS) {
        // segment 1: line interpolation  a + t*(b-a)
        int jj = j - NC;
        int lc = line_choice[b * NLS + jj];
        int s0 = lines_array[((long)(b * NC + lc)) * 2 + 0];
        int s1 = lines_array[((long)(b * NC + lc)) * 2 + 1];
        const float* A  = curves + ((long)(b * NC + s0)) * 3;
        const float* Bp = curves + ((long)(b * NC + s1)) * 3;
        float t = t_line[b * NLS + jj];
        p0 = __fadd_rn(A[0], __fmul_rn(t, __fsub_rn(Bp[0], A[0])));
        p1 = __fadd_rn(A[1], __fmul_rn(t, __fsub_rn(Bp[1], A[1])));
        p2 = __fadd_rn(A[2], __fmul_rn(t, __fsub_rn(Bp[2], A[2])));
    } else if (j < NC + NLS + NS) {
        // segment 2: surfaces passthrough
        int jj = j - (NC + NLS);
        const float* s = surfaces + ((long)(b * NS + jj)) * 3;
        p0 = s[0]; p1 = s[1]; p2 = s[2];
    } else {
        // segment 3: triangle barycentric sample
        int jj = j - (NC + NLS + NS);
        int tc = tri_choice[b * NTS + jj];
        const int* f = faces_array + ((long)(b * NF + tc)) * 3;
        const float* ta  = surfaces + ((long)(b * NS + f[0])) * 3;
        const float* tb  = surfaces + ((long)(b * NS + f[1])) * 3;
        const float* tcx = surfaces + ((long)(b * NS + f[2])) * 3;
        float u = uv[((long)(b * NTS + jj)) * 2 + 0];
        float v = uv[((long)(b * NTS + jj)) * 2 + 1];
        if (__fadd_rn(u, v) > 1.0f) {
            u = __fsub_rn(1.0f, u);
            v = __fsub_rn(1.0f, v);
        }
        // (ta + u*(tb-ta)) + v*(tc-ta), exact reference op order
        p0 = __fadd_rn(__fadd_rn(ta[0], __fmul_rn(u, __fsub_rn(tb[0], ta[0]))),
                       __fmul_rn(v, __fsub_rn(tcx[0], ta[0])));
        p1 = __fadd_rn(__fadd_rn(ta[1], __fmul_rn(u, __fsub_rn(tb[1], ta[1]))),
                       __fmul_rn(v, __fsub_rn(tcx[1], ta[1])));
        p2 = __fadd_rn(__fadd_rn(ta[2], __fmul_rn(u, __fsub_rn(tb[2], ta[2]))),
                       __fmul_rn(v, __fsub_rn(tcx[2], ta[2])));
    }

    float* xo = out + ((long)idx) * 3;
    xo[0] = p0; xo[1] = p1; xo[2] = p2;

    int c0 = cube_coord(p0);
    int c1 = cube_coord(p1);
    int c2 = cube_coord(p2);
    g_coords[idx] = c0 | (c1 << 8) | (c2 << 16);
}

// Grid-stride lane-contiguous zero of one slab (nblocks zero-blocks).
__device__ __forceinline__ void zero_slab(float4* __restrict__ p4,
                                          int blk, int nblocks) {
    int stride = nblocks * 256;
    const float4 z = make_float4(0.f, 0.f, 0.f, 0.f);
    for (int i = blk * 256 + threadIdx.x; i < N4_PER_B; i += stride)
        p4[i] = z;
}

// ---------------------------------------------------------------------------
// Kernel A (launch 0): points blocks [0, PTBLK) + grid-stride zero of slab 0
// in blocks [PTBLK, PTBLK+ZGB). Disjoint address sets; points' few-MB
// traffic is too small to disturb the streaming sweep.
// ---------------------------------------------------------------------------
__global__ void points_zero0_kernel(float* __restrict__ out,
                             const float* __restrict__ curves,
                             const float* __restrict__ surfaces,
                             const float* __restrict__ t_line,
                             const float* __restrict__ uv,
                             const int*   __restrict__ lines_array,
                             const int*   __restrict__ faces_array,
                             const int*   __restrict__ line_choice,
                             const int*   __restrict__ tri_choice) {
    if ((int)blockIdx.x < PTBLK) {
        int idx = blockIdx.x * blockDim.x + threadIdx.x;
        if (idx < NPTOT)
            points_job(idx, curves, surfaces, t_line, uv,
                       lines_array, faces_array, line_choice, tri_choice, out);
        return;
    }
    zero_slab((float4*)(out + X_ELEMS), (int)blockIdx.x - PTBLK, ZGB);
}

// ---------------------------------------------------------------------------
// Zero kernel: grid-stride float4 zero of slab b.
// ---------------------------------------------------------------------------
__global__ void zero_batch_kernel(float4* __restrict__ p) {
    zero_slab(p, (int)blockIdx.x, ZGB);
}

// ---------------------------------------------------------------------------
// Scatter kernel for one batch, 2-way point ILP: each thread handles rows
// (d0,d1) for TWO points (pidx, pidx+NPT2). The two packed-coord loads are
// independent and coalesced (MLP=2), hiding L2 latency; then 6 row-stores.
// Runs immediately after the slab's zero -> touched lines are L2-resident
// (dirty): stores are L2 partial-sector hits, no DRAM RMW. Dilation ==
// padded 3-maxpool of the one-hot grid; coords always in-bounds; writes
// idempotent 1.0f -> no races.
// ---------------------------------------------------------------------------
__global__ void scatter_batch_kernel(float* __restrict__ occ, int b) {
    int t = blockIdx.x * blockDim.x + threadIdx.x;
    if (t >= SCTHREADS) return;
    int r = t / NPT2;                // 0..8
    int pidx = t - r * NPT2;         // 0..16999
    int d0 = r / 3;
    int d1 = r - d0 * 3;

    const int* coords = g_coords + b * NPT;
    int pk0 = coords[pidx];          // independent, coalesced
    int pk1 = coords[pidx + NPT2];   // independent, coalesced (MLP=2)

    {
        int c0 = pk0 & 0xFF, c1 = (pk0 >> 8) & 0xFF, c2 = (pk0 >> 16) & 0xFF;
        float* row = occ + (long)(c0 + d0) * OGSQ + (long)(c1 + d1) * OG + c2;
        row[0] = 1.0f; row[1] = 1.0f; row[2] = 1.0f;
    }
    {
        int c0 = pk1 & 0xFF, c1 = (pk1 >> 8) & 0xFF, c2 = (pk1 >> 16) & 0xFF;
        float* row = occ + (long)(c0 + d0) * OGSQ + (long)(c1 + d1) * OG + c2;
        row[0] = 1.0f; row[1] = 1.0f; row[2] = 1.0f;
    }
}

extern "C" void kernel_launch(void* const* d_in, const int* in_sizes, int n_in,
                              void* d_out, int out_size) {
    // metadata order:
    // 0 imgs (unused), 1 curves, 2 surfaces, 3 t_line, 4 uv,
    // 5 lines_array, 6 faces_array, 7 indices_array (unused),
    // 8 line_choice, 9 tri_choice
    const float* curves      = (const float*)d_in[1];
    const float* surfaces    = (const float*)d_in[2];
    const float* t_line      = (const float*)d_in[3];
    const float* uv          = (const float*)d_in[4];
    const int*   lines_array = (const int*)d_in[5];
    const int*   faces_array = (const int*)d_in[6];
    const int*   line_choice = (const int*)d_in[8];
    const int*   tri_choice  = (const int*)d_in[9];
    float* out = (float*)d_out;

    // k0: points || zero slab 0
    points_zero0_kernel<<<PTBLK + ZGB, 256>>>(out, curves, surfaces, t_line,
                                              uv, lines_array, faces_array,
                                              line_choice, tri_choice);
    // scatter slab 0 (slab 0 L2-resident from k0)
    scatter_batch_kernel<<<SCB, 256>>>(out + X_ELEMS, 0);

    // slabs 1..3: zero then scatter (proven choreography)
    for (int b = 1; b < NB; b++) {
        float* occ_b = out + X_ELEMS + (long)b * OCC_PER_B;
        zero_batch_kernel<<<ZGB, 256>>>((float4*)occ_b);
        scatter_batch_kernel<<<SCB, 256>>>(occ_b, b);
    }
}